// round 12
// baseline (speedup 1.0000x reference)
#include <cuda_runtime.h>
#include <cuda_fp16.h>
#include <cstdint>

#define N_TOK 4096
#define D_IN  1024
#define D_HID 4096
#define D_OUT 1024
#define N_EXP 8

// ---------------- scratch (device globals; no runtime allocation) ----------------
__device__ __half g_Xh[(size_t)N_TOK * D_IN];            // x in fp16
__device__ __half g_W1h[(size_t)N_EXP * D_HID * D_IN];   // W1^T per expert: [e][N=4096][K=1024]
__device__ __half g_W2h[(size_t)N_EXP * D_OUT * D_HID];  // W2^T per expert: [e][N=1024][K=4096]
__device__ __half g_Hh[(size_t)N_TOK * 2 * D_HID];       // hidden acts fp16 per slot
__device__ float  g_topk_w[N_TOK * 2];
__device__ int    g_count[N_EXP];
__device__ int    g_slots[N_EXP * N_TOK];                // slot = 2*token + k
__device__ int    g_ready[N_EXP * 32];                   // per-(e,mt) completed f1 n-tiles
__device__ int    g_w2done;                              // completed ctW2 tiles

// ---------------- helpers ----------------
__device__ __forceinline__ uint32_t s2u(const void* p) {
    return (uint32_t)__cvta_generic_to_shared(p);
}
__device__ __forceinline__ void cpa16(uint32_t d, const void* g) {
    asm volatile("cp.async.cg.shared.global [%0], [%1], 16;\n" :: "r"(d), "l"(g));
}
#define LDSM_X4(r, a) \
    asm("ldmatrix.sync.aligned.m8n8.x4.shared.b16 {%0,%1,%2,%3}, [%4];" \
        : "=r"((r)[0]), "=r"((r)[1]), "=r"((r)[2]), "=r"((r)[3]) : "r"(a) : "memory")

__device__ __forceinline__ void mma_f16(float* d, const uint32_t* a, const uint32_t* b) {
    asm("mma.sync.aligned.m16n8k16.row.col.f32.f16.f16.f32 "
        "{%0,%1,%2,%3}, {%4,%5,%6,%7}, {%8,%9}, {%0,%1,%2,%3};"
        : "+f"(d[0]), "+f"(d[1]), "+f"(d[2]), "+f"(d[3])
        : "r"(a[0]), "r"(a[1]), "r"(a[2]), "r"(a[3]),
          "r"(b[0]), "r"(b[1]));
}
__device__ __forceinline__ void redadd(float* p, float v) {
    asm volatile("red.global.add.f32 [%0], %1;" :: "l"(p), "f"(v) : "memory");
}

// ---------------- init0: zero counters (must precede gating atomics / readiness) ----------------
__global__ void init0_kernel() {
    int t = threadIdx.x;
    if (t < N_EXP) g_count[t] = 0;
    if (t < N_EXP * 32) g_ready[t] = 0;
    if (t == 256) g_w2done = 0;
}

// ============ shared device bodies ============

template <int K, int N>
__device__ __forceinline__ void transpose_tile_256(const float* __restrict__ S,
                                                   __half* __restrict__ D,
                                                   int n0, int k0, float (*t)[65], int tid) {
    const int tx = tid & 31, ty = tid >> 5;   // 32 x 8
#pragma unroll
    for (int j = 0; j < 64; j += 8) {
        t[ty + j][tx]      = S[(size_t)(k0 + ty + j) * N + n0 + tx];
        t[ty + j][tx + 32] = S[(size_t)(k0 + ty + j) * N + n0 + tx + 32];
    }
    __syncthreads();
#pragma unroll
    for (int p = 0; p < 2; p++) {
        int n = p * 32 + (tid >> 3);
        int m = tid & 7;
        float f[8];
#pragma unroll
        for (int i = 0; i < 8; i++) f[i] = t[8 * m + i][n];
        half2 hh[4];
        hh[0] = __floats2half2_rn(f[0], f[1]);
        hh[1] = __floats2half2_rn(f[2], f[3]);
        hh[2] = __floats2half2_rn(f[4], f[5]);
        hh[3] = __floats2half2_rn(f[6], f[7]);
        *(uint4*)(D + (size_t)(n0 + n) * K + k0 + 8 * m) = *(uint4*)hh;
    }
}

template <int K, int N>
__device__ __forceinline__ void transpose_tile_128(const float* __restrict__ S,
                                                   __half* __restrict__ D,
                                                   int n0, int k0, float (*t)[65], int tid) {
    const int tx = tid & 31, ty = tid >> 5;   // 32 x 4
#pragma unroll
    for (int j = 0; j < 64; j += 4) {
        t[ty + j][tx]      = S[(size_t)(k0 + ty + j) * N + n0 + tx];
        t[ty + j][tx + 32] = S[(size_t)(k0 + ty + j) * N + n0 + tx + 32];
    }
    __syncthreads();
#pragma unroll
    for (int p = 0; p < 4; p++) {
        int n = p * 16 + (tid >> 3);
        int m = tid & 7;
        float f[8];
#pragma unroll
        for (int i = 0; i < 8; i++) f[i] = t[8 * m + i][n];
        half2 hh[4];
        hh[0] = __floats2half2_rn(f[0], f[1]);
        hh[1] = __floats2half2_rn(f[2], f[3]);
        hh[2] = __floats2half2_rn(f[4], f[5]);
        hh[3] = __floats2half2_rn(f[6], f[7]);
        *(uint4*)(D + (size_t)(n0 + n) * K + k0 + 8 * m) = *(uint4*)hh;
    }
}

// ---------------- P1: fused ctW1 + gating(+x->fp16) + out-zero ----------------
__global__ void __launch_bounds__(256)
prep_kernel(const float* __restrict__ x,  const float* __restrict__ W1,
            const float* __restrict__ Wg, const float* __restrict__ bg,
            float* __restrict__ out) {
    __shared__ float t[64][65];
    const int bid = blockIdx.x;
    const int tid = threadIdx.x;

    if (bid < 8192) {                       // ---- transpose W1 tile ----
        const int e = bid >> 10, tile = bid & 1023;
        const int nt = tile >> 4, kt = tile & 15;
        transpose_tile_256<D_IN, D_HID>(W1 + (size_t)e * D_IN * D_HID,
                                        g_W1h + (size_t)e * D_HID * D_IN,
                                        nt * 64, kt * 64, t, tid);
        return;
    }
    if (bid >= 8704) {                      // ---- zero out ----
        int i = (bid - 8704) * 256 + tid;
        ((float4*)out)[i] = make_float4(0.f, 0.f, 0.f, 0.f);
        return;
    }

    // ---- gating + x->fp16 for 8 tokens ----
    const int tb   = (bid - 8192) * 8;
    const int tok  = tb + (tid >> 5);
    const int lane = tid & 31;
    {
        const float4* xv = (const float4*)(x + (size_t)tb * D_IN);
        half2* xo = (half2*)(g_Xh + (size_t)tb * D_IN);
#pragma unroll
        for (int i = tid; i < 8 * D_IN / 4; i += 256) {
            float4 v = xv[i];
            xo[2 * i]     = __floats2half2_rn(v.x, v.y);
            xo[2 * i + 1] = __floats2half2_rn(v.z, v.w);
        }
    }

    float acc[8];
#pragma unroll
    for (int e = 0; e < 8; e++) acc[e] = 0.f;
    const float* xr = x + (size_t)tok * D_IN;
    for (int d = lane; d < D_IN; d += 32) {
        float xv = xr[d];
        float4 w0 = *(const float4*)(Wg + d * 8);
        float4 w1 = *(const float4*)(Wg + d * 8 + 4);
        acc[0] += xv * w0.x; acc[1] += xv * w0.y;
        acc[2] += xv * w0.z; acc[3] += xv * w0.w;
        acc[4] += xv * w1.x; acc[5] += xv * w1.y;
        acc[6] += xv * w1.z; acc[7] += xv * w1.w;
    }
#pragma unroll
    for (int off = 16; off > 0; off >>= 1)
#pragma unroll
        for (int e = 0; e < 8; e++)
            acc[e] += __shfl_xor_sync(0xFFFFFFFFu, acc[e], off);

    if (lane == 0) {
        float l[8];
#pragma unroll
        for (int e = 0; e < 8; e++) l[e] = acc[e] + bg[e];
        float mx = l[0];
#pragma unroll
        for (int e = 1; e < 8; e++) mx = fmaxf(mx, l[e]);
        float p[8], s = 0.f;
#pragma unroll
        for (int e = 0; e < 8; e++) { p[e] = expf(l[e] - mx); s += p[e]; }
        float inv = 1.f / s;
#pragma unroll
        for (int e = 0; e < 8; e++) p[e] *= inv;

        int i0 = 0; float v0 = p[0];
#pragma unroll
        for (int e = 1; e < 8; e++) if (p[e] > v0) { v0 = p[e]; i0 = e; }
        int i1 = -1; float v1 = -1.f;
#pragma unroll
        for (int e = 0; e < 8; e++) if (e != i0 && p[e] > v1) { v1 = p[e]; i1 = e; }

        float e1 = expf(v1 - v0);
        float den = 1.f / (1.f + e1);
        int p0 = atomicAdd(&g_count[i0], 1);
        g_slots[i0 * N_TOK + p0] = 2 * tok;
        int p1 = atomicAdd(&g_count[i1], 1);
        g_slots[i1 * N_TOK + p1] = 2 * tok + 1;
        g_topk_w[2 * tok]     = den;
        g_topk_w[2 * tok + 1] = e1 * den;
    }
}

// ---------------- ffn GEMM body: 128x128x64 tile, 128 threads, 3-stage pipeline ----------------
template <bool FIRST>
__device__ __forceinline__ void ffn_body(int e, int m0, int n0,
                                         const float* __restrict__ Bias,
                                         float* __restrict__ out, char* smem) {
    constexpr int K  = FIRST ? D_IN : D_HID;
    constexpr int N  = FIRST ? D_HID : D_OUT;
    constexpr int BM = 128, BK = 64;
    constexpr int STRB = (BK + 8) * 2;     // 144 bytes/row
    constexpr int NS = K / BK;
    constexpr int ASTG = BM * STRB;        // 18432 B per stage

    constexpr int OFF_SLOT = 0;
    constexpr int OFF_A    = 1024;                 // 3 stages
    constexpr int OFF_B    = 1024 + 3 * ASTG;      // 3 stages

    const uint32_t su = s2u(smem);
    const int cnt = g_count[e];
    const int rows = min(BM, cnt - m0);

    const int tid  = threadIdx.x;
    const int lane = tid & 31;
    const int warp = tid >> 5;
    const int gid  = lane >> 2;
    const int itg  = lane & 3;
    const int wm = warp >> 1;
    const int wn = warp & 1;

    int* sSlot = (int*)(smem + OFF_SLOT);
    sSlot[tid] = g_slots[e * N_TOK + m0 + ((tid < rows) ? tid : 0)];
    __syncthreads();

    const __half* Wb = (FIRST ? g_W1h : g_W2h)
                     + (size_t)e * (size_t)N * K + (size_t)n0 * K;

    auto stage = [&](int s) {
        const int k0 = s * BK;
        const int sl = s % 3;
        const uint32_t ab = su + OFF_A + sl * ASTG;
        const uint32_t bb = su + OFF_B + sl * ASTG;
#pragma unroll
        for (int it = 0; it < 8; it++) {
            int idx = it * 128 + tid;
            int row = idx >> 3, c = idx & 7;
            int slot = sSlot[row];
            const __half* g = FIRST
                ? g_Xh + (size_t)(slot >> 1) * D_IN  + k0 + c * 8
                : g_Hh + (size_t)slot        * D_HID + k0 + c * 8;
            cpa16(ab + row * STRB + c * 16, g);
        }
#pragma unroll
        for (int it = 0; it < 8; it++) {
            int idx = it * 128 + tid;
            int row = idx >> 3, c = idx & 7;
            cpa16(bb + row * STRB + c * 16, Wb + (size_t)row * K + k0 + c * 8);
        }
        asm volatile("cp.async.commit_group;\n");
    };

    float acc[4][8][4];
#pragma unroll
    for (int a = 0; a < 4; a++)
#pragma unroll
        for (int b = 0; b < 8; b++)
#pragma unroll
            for (int c = 0; c < 4; c++) acc[a][b][c] = 0.f;

    const uint32_t aLane = (uint32_t)((wm * 64 + (lane & 15)) * STRB + (lane >> 4) * 16);
    const uint32_t bLane = (uint32_t)((wn * 64 + (lane & 7) + ((lane & 16) ? 8 : 0)) * STRB
                                      + ((lane & 8) ? 16 : 0));

    stage(0);
    stage(1);
    for (int s = 0; s < NS; ++s) {
        if (s + 1 < NS) {
            asm volatile("cp.async.wait_group 1;\n");
        } else {
            asm volatile("cp.async.wait_group 0;\n");
        }
        __syncthreads();
        if (s + 2 < NS) stage(s + 2);

        const int sl = s % 3;
        const uint32_t aS = su + OFF_A + sl * ASTG + aLane;
        const uint32_t bS = su + OFF_B + sl * ASTG + bLane;

        uint32_t af[2][4][4], bf[2][4][4];
#pragma unroll
        for (int mf = 0; mf < 4; ++mf) LDSM_X4(af[0][mf], aS + mf * 16 * STRB);
#pragma unroll
        for (int p = 0; p < 4; ++p)    LDSM_X4(bf[0][p],  bS + p * 16 * STRB);

#pragma unroll
        for (int ks = 0; ks < BK / 16; ++ks) {
            const int cur = ks & 1, nxt = cur ^ 1;
            if (ks + 1 < BK / 16) {
#pragma unroll
                for (int mf = 0; mf < 4; ++mf)
                    LDSM_X4(af[nxt][mf], aS + (ks + 1) * 32 + mf * 16 * STRB);
#pragma unroll
                for (int p = 0; p < 4; ++p)
                    LDSM_X4(bf[nxt][p],  bS + (ks + 1) * 32 + p * 16 * STRB);
            }
#pragma unroll
            for (int mf = 0; mf < 4; ++mf)
#pragma unroll
                for (int p = 0; p < 4; ++p) {
                    mma_f16(acc[mf][2 * p],     af[cur][mf], &bf[cur][p][0]);
                    mma_f16(acc[mf][2 * p + 1], af[cur][mf], &bf[cur][p][2]);
                }
        }
    }

#pragma unroll
    for (int mf = 0; mf < 4; ++mf) {
        int rl = wm * 64 + mf * 16 + gid;
#pragma unroll
        for (int nf = 0; nf < 8; ++nf) {
            int n = n0 + wn * 64 + nf * 8 + 2 * itg;
            float2 bv = *(const float2*)(Bias + (size_t)e * N + n);
            float v00 = acc[mf][nf][0] + bv.x;
            float v01 = acc[mf][nf][1] + bv.y;
            float v10 = acc[mf][nf][2] + bv.x;
            float v11 = acc[mf][nf][3] + bv.y;
            if (FIRST) {
                v00 = fmaxf(v00, 0.f); v01 = fmaxf(v01, 0.f);
                v10 = fmaxf(v10, 0.f); v11 = fmaxf(v11, 0.f);
                if (rl < rows) {
                    int slot = sSlot[rl];
                    *(half2*)(g_Hh + (size_t)slot * D_HID + n) = __floats2half2_rn(v00, v01);
                }
                if (rl + 8 < rows) {
                    int slot = sSlot[rl + 8];
                    *(half2*)(g_Hh + (size_t)slot * D_HID + n) = __floats2half2_rn(v10, v11);
                }
            } else {
                if (rl < rows) {
                    int slot = sSlot[rl];
                    float w = g_topk_w[slot];
                    float* o = out + (size_t)(slot >> 1) * D_OUT + n;
                    redadd(o,     v00 * w);
                    redadd(o + 1, v01 * w);
                }
                if (rl + 8 < rows) {
                    int slot = sSlot[rl + 8];
                    float w = g_topk_w[slot];
                    float* o = out + (size_t)(slot >> 1) * D_OUT + n;
                    redadd(o,     v10 * w);
                    redadd(o + 1, v11 * w);
                }
            }
        }
    }
}

// ---------------- fused GEMM kernel: f1 + ctW2 + f2, ordered by bid ----------------
// bids [0,16384): even -> f1 tile (mt-major: active tiles first), odd -> ctW2 tile
// bids [16384,18432): f2 tile (mt-major), spin-waits on readiness
__global__ void __launch_bounds__(128, 2)
moe_gemm_kernel(const float* __restrict__ b1, const float* __restrict__ b2,
                const float* __restrict__ W2, float* __restrict__ out) {
    extern __shared__ __align__(128) char smem[];
    const int bid = blockIdx.x;
    const int tid = threadIdx.x;

    if (bid < 16384) {
        const int i = bid >> 1;
        if (!(bid & 1)) {
            // f1 tile: nt fastest, then e, then mt (active tiles = lowest bids)
            const int nt = i & 31, e = (i >> 5) & 7, mt = i >> 8;
            if (mt * 128 >= g_count[e]) return;
            ffn_body<true>(e, mt * 128, nt * 128, b1, nullptr, smem);
            __threadfence();              // release g_Hh stores (all threads)
            __syncthreads();
            if (tid == 0) atomicAdd(&g_ready[e * 32 + mt], 1);
        } else {
            // ctW2 tile
            const int e = i >> 10, tile = i & 1023;
            const int nt = tile & 15, kt = tile >> 4;
            transpose_tile_128<D_HID, D_OUT>(W2 + (size_t)e * D_HID * D_OUT,
                                             g_W2h + (size_t)e * D_OUT * D_HID,
                                             nt * 64, kt * 64, (float(*)[65])smem, tid);
            __threadfence();
            __syncthreads();
            if (tid == 0) atomicAdd(&g_w2done, 1);
        }
    } else {
        // f2 tile: nt fastest, then e, then mt
        const int j = bid - 16384;
        const int nt = j & 7, e = (j >> 3) & 7, mt = j >> 6;
        if (mt * 128 >= g_count[e]) return;
        if (tid == 0) {
            while (*(volatile int*)&g_w2done < 8192) __nanosleep(128);
            while (*(volatile int*)&g_ready[e * 32 + mt] < 32) __nanosleep(128);
            __threadfence();              // acquire
        }
        __syncthreads();
        ffn_body<false>(e, mt * 128, nt * 128, b2, out, smem);
    }
}

// ---------------- launch ----------------
extern "C" void kernel_launch(void* const* d_in, const int* in_sizes, int n_in,
                              void* d_out, int out_size) {
    const float* x  = (const float*)d_in[0];
    const float* W1 = (const float*)d_in[1];
    const float* b1 = (const float*)d_in[2];
    const float* W2 = (const float*)d_in[3];
    const float* b2 = (const float*)d_in[4];
    const float* Wg = (const float*)d_in[5];
    const float* bg = (const float*)d_in[6];
    float* out = (float*)d_out;

    constexpr int SMEM_FFN = 1024 + 6 * 128 * 144;   // 111616 -> 2 CTAs/SM
    cudaFuncSetAttribute(moe_gemm_kernel,
                         cudaFuncAttributeMaxDynamicSharedMemorySize, SMEM_FFN);

    init0_kernel<<<1, 288>>>();
    prep_kernel<<<12800, 256>>>(x, W1, Wg, bg, out);
    moe_gemm_kernel<<<16384 + 2048, 128, SMEM_FFN>>>(b1, b2, W2, out);
}

// round 13
// speedup vs baseline: 1.0093x; 1.0093x over previous
#include <cuda_runtime.h>
#include <cuda_fp16.h>
#include <cstdint>

#define N_TOK 4096
#define D_IN  1024
#define D_HID 4096
#define D_OUT 1024
#define N_EXP 8

// ---------------- scratch (device globals; no runtime allocation) ----------------
__device__ __half g_Xh[(size_t)N_TOK * D_IN];            // x in fp16
__device__ __half g_W1h[(size_t)N_EXP * D_HID * D_IN];   // W1^T per expert: [e][N=4096][K=1024]
__device__ __half g_W2h[(size_t)N_EXP * D_OUT * D_HID];  // W2^T per expert: [e][N=1024][K=4096]
__device__ __half g_Hh[(size_t)N_TOK * 2 * D_HID];       // hidden acts fp16 per slot
__device__ float  g_topk_w[N_TOK * 2];
__device__ int    g_count[N_EXP];
__device__ int    g_slots[N_EXP * N_TOK];                // slot = 2*token + k

// ---------------- helpers ----------------
__device__ __forceinline__ uint32_t s2u(const void* p) {
    return (uint32_t)__cvta_generic_to_shared(p);
}
__device__ __forceinline__ void cpa16(uint32_t d, const void* g) {
    asm volatile("cp.async.cg.shared.global [%0], [%1], 16;\n" :: "r"(d), "l"(g));
}
#define LDSM_X4(r, a) \
    asm("ldmatrix.sync.aligned.m8n8.x4.shared.b16 {%0,%1,%2,%3}, [%4];" \
        : "=r"((r)[0]), "=r"((r)[1]), "=r"((r)[2]), "=r"((r)[3]) : "r"(a) : "memory")

__device__ __forceinline__ void mma_f16(float* d, const uint32_t* a, const uint32_t* b) {
    asm("mma.sync.aligned.m16n8k16.row.col.f32.f16.f16.f32 "
        "{%0,%1,%2,%3}, {%4,%5,%6,%7}, {%8,%9}, {%0,%1,%2,%3};"
        : "+f"(d[0]), "+f"(d[1]), "+f"(d[2]), "+f"(d[3])
        : "r"(a[0]), "r"(a[1]), "r"(a[2]), "r"(a[3]),
          "r"(b[0]), "r"(b[1]));
}
__device__ __forceinline__ void redadd(float* p, float v) {
    asm volatile("red.global.add.f32 [%0], %1;" :: "l"(p), "f"(v) : "memory");
}

// ---------------- init0: zero expert counters (must precede gating atomics) ----------------
__global__ void init0_kernel() {
    if (threadIdx.x < N_EXP) g_count[threadIdx.x] = 0;
}

// ============ shared device bodies ============

template <int K, int N>
__device__ __forceinline__ void transpose_tile_256(const float* __restrict__ S,
                                                   __half* __restrict__ D,
                                                   int n0, int k0, float (*t)[65], int tid) {
    const int tx = tid & 31, ty = tid >> 5;   // 32 x 8
#pragma unroll
    for (int j = 0; j < 64; j += 8) {
        t[ty + j][tx]      = S[(size_t)(k0 + ty + j) * N + n0 + tx];
        t[ty + j][tx + 32] = S[(size_t)(k0 + ty + j) * N + n0 + tx + 32];
    }
    __syncthreads();
#pragma unroll
    for (int p = 0; p < 2; p++) {
        int n = p * 32 + (tid >> 3);
        int m = tid & 7;
        float f[8];
#pragma unroll
        for (int i = 0; i < 8; i++) f[i] = t[8 * m + i][n];
        half2 hh[4];
        hh[0] = __floats2half2_rn(f[0], f[1]);
        hh[1] = __floats2half2_rn(f[2], f[3]);
        hh[2] = __floats2half2_rn(f[4], f[5]);
        hh[3] = __floats2half2_rn(f[6], f[7]);
        *(uint4*)(D + (size_t)(n0 + n) * K + k0 + 8 * m) = *(uint4*)hh;
    }
}

template <int K, int N>
__device__ __forceinline__ void transpose_tile_128(const float* __restrict__ S,
                                                   __half* __restrict__ D,
                                                   int n0, int k0, float (*t)[65], int tid) {
    const int tx = tid & 31, ty = tid >> 5;   // 32 x 4
#pragma unroll
    for (int j = 0; j < 64; j += 4) {
        t[ty + j][tx]      = S[(size_t)(k0 + ty + j) * N + n0 + tx];
        t[ty + j][tx + 32] = S[(size_t)(k0 + ty + j) * N + n0 + tx + 32];
    }
    __syncthreads();
#pragma unroll
    for (int p = 0; p < 4; p++) {
        int n = p * 16 + (tid >> 3);
        int m = tid & 7;
        float f[8];
#pragma unroll
        for (int i = 0; i < 8; i++) f[i] = t[8 * m + i][n];
        half2 hh[4];
        hh[0] = __floats2half2_rn(f[0], f[1]);
        hh[1] = __floats2half2_rn(f[2], f[3]);
        hh[2] = __floats2half2_rn(f[4], f[5]);
        hh[3] = __floats2half2_rn(f[6], f[7]);
        *(uint4*)(D + (size_t)(n0 + n) * K + k0 + 8 * m) = *(uint4*)hh;
    }
}

// ---------------- P1: fused ctW1 + gating(+x->fp16) + out-zero ----------------
__global__ void __launch_bounds__(256)
prep_kernel(const float* __restrict__ x,  const float* __restrict__ W1,
            const float* __restrict__ Wg, const float* __restrict__ bg,
            float* __restrict__ out) {
    __shared__ float t[64][65];
    const int bid = blockIdx.x;
    const int tid = threadIdx.x;

    if (bid < 8192) {                       // ---- transpose W1 tile ----
        const int e = bid >> 10, tile = bid & 1023;
        const int nt = tile >> 4, kt = tile & 15;
        transpose_tile_256<D_IN, D_HID>(W1 + (size_t)e * D_IN * D_HID,
                                        g_W1h + (size_t)e * D_HID * D_IN,
                                        nt * 64, kt * 64, t, tid);
        return;
    }
    if (bid >= 8704) {                      // ---- zero out ----
        int i = (bid - 8704) * 256 + tid;
        ((float4*)out)[i] = make_float4(0.f, 0.f, 0.f, 0.f);
        return;
    }

    // ---- gating + x->fp16 for 8 tokens ----
    const int tb   = (bid - 8192) * 8;
    const int tok  = tb + (tid >> 5);
    const int lane = tid & 31;
    {
        const float4* xv = (const float4*)(x + (size_t)tb * D_IN);
        half2* xo = (half2*)(g_Xh + (size_t)tb * D_IN);
#pragma unroll
        for (int i = tid; i < 8 * D_IN / 4; i += 256) {
            float4 v = xv[i];
            xo[2 * i]     = __floats2half2_rn(v.x, v.y);
            xo[2 * i + 1] = __floats2half2_rn(v.z, v.w);
        }
    }

    float acc[8];
#pragma unroll
    for (int e = 0; e < 8; e++) acc[e] = 0.f;
    const float* xr = x + (size_t)tok * D_IN;
    for (int d = lane; d < D_IN; d += 32) {
        float xv = xr[d];
        float4 w0 = *(const float4*)(Wg + d * 8);
        float4 w1 = *(const float4*)(Wg + d * 8 + 4);
        acc[0] += xv * w0.x; acc[1] += xv * w0.y;
        acc[2] += xv * w0.z; acc[3] += xv * w0.w;
        acc[4] += xv * w1.x; acc[5] += xv * w1.y;
        acc[6] += xv * w1.z; acc[7] += xv * w1.w;
    }
#pragma unroll
    for (int off = 16; off > 0; off >>= 1)
#pragma unroll
        for (int e = 0; e < 8; e++)
            acc[e] += __shfl_xor_sync(0xFFFFFFFFu, acc[e], off);

    if (lane == 0) {
        float l[8];
#pragma unroll
        for (int e = 0; e < 8; e++) l[e] = acc[e] + bg[e];
        float mx = l[0];
#pragma unroll
        for (int e = 1; e < 8; e++) mx = fmaxf(mx, l[e]);
        float p[8], s = 0.f;
#pragma unroll
        for (int e = 0; e < 8; e++) { p[e] = expf(l[e] - mx); s += p[e]; }
        float inv = 1.f / s;
#pragma unroll
        for (int e = 0; e < 8; e++) p[e] *= inv;

        int i0 = 0; float v0 = p[0];
#pragma unroll
        for (int e = 1; e < 8; e++) if (p[e] > v0) { v0 = p[e]; i0 = e; }
        int i1 = -1; float v1 = -1.f;
#pragma unroll
        for (int e = 0; e < 8; e++) if (e != i0 && p[e] > v1) { v1 = p[e]; i1 = e; }

        float e1 = expf(v1 - v0);
        float den = 1.f / (1.f + e1);
        int p0 = atomicAdd(&g_count[i0], 1);
        g_slots[i0 * N_TOK + p0] = 2 * tok;
        int p1 = atomicAdd(&g_count[i1], 1);
        g_slots[i1 * N_TOK + p1] = 2 * tok + 1;
        g_topk_w[2 * tok]     = den;
        g_topk_w[2 * tok + 1] = e1 * den;
    }
}

// ---------------- ffn GEMM body: 128x128x64 tile, 3-stage smem ring,
// ---------------- cross-stage fragment pipeline (stage-boundary work hides under tail HMMAs)
template <bool FIRST>
__device__ __forceinline__ void ffn_body(int e, int m0, int n0,
                                         const float* __restrict__ Bias,
                                         float* __restrict__ out, char* smem) {
    constexpr int K  = FIRST ? D_IN : D_HID;
    constexpr int N  = FIRST ? D_HID : D_OUT;
    constexpr int BM = 128, BK = 64;
    constexpr int STRB = (BK + 8) * 2;     // 144 bytes/row
    constexpr int NS = K / BK;
    constexpr int ASTG = BM * STRB;        // 18432 B per stage

    constexpr int OFF_SLOT = 0;
    constexpr int OFF_A    = 1024;                 // 3 stages
    constexpr int OFF_B    = 1024 + 3 * ASTG;      // 3 stages

    const uint32_t su = s2u(smem);
    const int cnt = g_count[e];
    const int rows = min(BM, cnt - m0);

    const int tid  = threadIdx.x;
    const int lane = tid & 31;
    const int warp = tid >> 5;
    const int gid  = lane >> 2;
    const int itg  = lane & 3;
    const int wm = warp >> 1;
    const int wn = warp & 1;

    int* sSlot = (int*)(smem + OFF_SLOT);
    sSlot[tid] = g_slots[e * N_TOK + m0 + ((tid < rows) ? tid : 0)];
    __syncthreads();

    const __half* Wb = (FIRST ? g_W1h : g_W2h)
                     + (size_t)e * (size_t)N * K + (size_t)n0 * K;

    auto stage = [&](int s) {
        const int k0 = s * BK;
        const int sl = s % 3;
        const uint32_t ab = su + OFF_A + sl * ASTG;
        const uint32_t bb = su + OFF_B + sl * ASTG;
#pragma unroll
        for (int it = 0; it < 8; it++) {
            int idx = it * 128 + tid;
            int row = idx >> 3, c = idx & 7;
            int slot = sSlot[row];
            const __half* g = FIRST
                ? g_Xh + (size_t)(slot >> 1) * D_IN  + k0 + c * 8
                : g_Hh + (size_t)slot        * D_HID + k0 + c * 8;
            cpa16(ab + row * STRB + c * 16, g);
        }
#pragma unroll
        for (int it = 0; it < 8; it++) {
            int idx = it * 128 + tid;
            int row = idx >> 3, c = idx & 7;
            cpa16(bb + row * STRB + c * 16, Wb + (size_t)row * K + k0 + c * 8);
        }
        asm volatile("cp.async.commit_group;\n");
    };

    float acc[4][8][4];
#pragma unroll
    for (int a = 0; a < 4; a++)
#pragma unroll
        for (int b = 0; b < 8; b++)
#pragma unroll
            for (int c = 0; c < 4; c++) acc[a][b][c] = 0.f;

    const uint32_t aLane = (uint32_t)((wm * 64 + (lane & 15)) * STRB + (lane >> 4) * 16);
    const uint32_t bLane = (uint32_t)((wn * 64 + (lane & 7) + ((lane & 16) ? 8 : 0)) * STRB
                                      + ((lane & 8) ? 16 : 0));

    uint32_t af[2][4][4], bf[2][4][4];

    auto ldsm_ks = [&](int buf, int sl, int ks) {
        const uint32_t aS = su + OFF_A + sl * ASTG + aLane + ks * 32;
        const uint32_t bS = su + OFF_B + sl * ASTG + bLane + ks * 32;
#pragma unroll
        for (int mf = 0; mf < 4; ++mf) LDSM_X4(af[buf][mf], aS + mf * 16 * STRB);
#pragma unroll
        for (int p = 0; p < 4; ++p)    LDSM_X4(bf[buf][p],  bS + p * 16 * STRB);
    };

    // prologue: commit 0,1; wait group 0; barrier; commit 2; load frags (s=0,ks=0)
    stage(0);
    stage(1);
    asm volatile("cp.async.wait_group 1;\n");
    __syncthreads();
    stage(2);                      // NS >= 16 always
    ldsm_ks(0, 0, 0);

    // mainloop: cur = ks&1 (4s even). At ks==3 the stage boundary
    // (wait+barrier+commit+next-stage LDSM) is issued BEFORE the tail HMMAs,
    // hiding the LDSM latency under them.
    for (int s = 0; s < NS; ++s) {
        const int sl = s % 3;
#pragma unroll
        for (int ks = 0; ks < 4; ++ks) {
            const int cur = ks & 1, nxt = cur ^ 1;
            if (ks < 3) {
                ldsm_ks(nxt, sl, ks + 1);
            } else if (s + 1 < NS) {
                if (s + 1 == NS - 1) {
                    asm volatile("cp.async.wait_group 0;\n");
                } else {
                    asm volatile("cp.async.wait_group 1;\n");
                }
                __syncthreads();
                if (s + 3 < NS) stage(s + 3);
                ldsm_ks(nxt, (s + 1) % 3, 0);
            }
#pragma unroll
            for (int mf = 0; mf < 4; ++mf)
#pragma unroll
                for (int p = 0; p < 4; ++p) {
                    mma_f16(acc[mf][2 * p],     af[cur][mf], &bf[cur][p][0]);
                    mma_f16(acc[mf][2 * p + 1], af[cur][mf], &bf[cur][p][2]);
                }
        }
    }

#pragma unroll
    for (int mf = 0; mf < 4; ++mf) {
        int rl = wm * 64 + mf * 16 + gid;
#pragma unroll
        for (int nf = 0; nf < 8; ++nf) {
            int n = n0 + wn * 64 + nf * 8 + 2 * itg;
            float2 bv = *(const float2*)(Bias + (size_t)e * N + n);
            float v00 = acc[mf][nf][0] + bv.x;
            float v01 = acc[mf][nf][1] + bv.y;
            float v10 = acc[mf][nf][2] + bv.x;
            float v11 = acc[mf][nf][3] + bv.y;
            if (FIRST) {
                v00 = fmaxf(v00, 0.f); v01 = fmaxf(v01, 0.f);
                v10 = fmaxf(v10, 0.f); v11 = fmaxf(v11, 0.f);
                if (rl < rows) {
                    int slot = sSlot[rl];
                    *(half2*)(g_Hh + (size_t)slot * D_HID + n) = __floats2half2_rn(v00, v01);
                }
                if (rl + 8 < rows) {
                    int slot = sSlot[rl + 8];
                    *(half2*)(g_Hh + (size_t)slot * D_HID + n) = __floats2half2_rn(v10, v11);
                }
            } else {
                if (rl < rows) {
                    int slot = sSlot[rl];
                    float w = g_topk_w[slot];
                    float* o = out + (size_t)(slot >> 1) * D_OUT + n;
                    redadd(o,     v00 * w);
                    redadd(o + 1, v01 * w);
                }
                if (rl + 8 < rows) {
                    int slot = sSlot[rl + 8];
                    float w = g_topk_w[slot];
                    float* o = out + (size_t)(slot >> 1) * D_OUT + n;
                    redadd(o,     v10 * w);
                    redadd(o + 1, v11 * w);
                }
            }
        }
    }
}

// ---------------- F1: ffn layer 1 interleaved with ctW2 (roles alternate by bid&1) ----------------
__global__ void __launch_bounds__(128, 2)
f1_kernel(const float* __restrict__ b1, const float* __restrict__ W2) {
    extern __shared__ __align__(128) char smem[];
    const int bid = blockIdx.x;
    const int i = bid >> 1;
    if (!(bid & 1)) {
        const int nt = i & 31, mt = (i >> 5) & 31, e = i >> 10;
        if (mt * 128 >= g_count[e]) return;
        ffn_body<true>(e, mt * 128, nt * 128, b1, nullptr, smem);
    } else {
        const int e = i >> 10, tile = i & 1023;
        const int nt = tile & 15, kt = tile >> 4;
        transpose_tile_128<D_HID, D_OUT>(W2 + (size_t)e * D_HID * D_OUT,
                                         g_W2h + (size_t)e * D_OUT * D_HID,
                                         nt * 64, kt * 64, (float(*)[65])smem, threadIdx.x);
    }
}

// ---------------- F2: ffn layer 2 (+fused combine via red.add) ----------------
__global__ void __launch_bounds__(128, 2)
f2_kernel(const float* __restrict__ b2, float* __restrict__ out) {
    extern __shared__ __align__(128) char smem[];
    const int e = blockIdx.z, mt = blockIdx.y, nt = blockIdx.x;
    if (mt * 128 >= g_count[e]) return;
    ffn_body<false>(e, mt * 128, nt * 128, b2, out, smem);
}

// ---------------- launch ----------------
extern "C" void kernel_launch(void* const* d_in, const int* in_sizes, int n_in,
                              void* d_out, int out_size) {
    const float* x  = (const float*)d_in[0];
    const float* W1 = (const float*)d_in[1];
    const float* b1 = (const float*)d_in[2];
    const float* W2 = (const float*)d_in[3];
    const float* b2 = (const float*)d_in[4];
    const float* Wg = (const float*)d_in[5];
    const float* bg = (const float*)d_in[6];
    float* out = (float*)d_out;

    constexpr int SMEM_FFN = 1024 + 6 * 128 * 144;   // 111616 -> 2 CTAs/SM
    cudaFuncSetAttribute(f1_kernel, cudaFuncAttributeMaxDynamicSharedMemorySize, SMEM_FFN);
    cudaFuncSetAttribute(f2_kernel, cudaFuncAttributeMaxDynamicSharedMemorySize, SMEM_FFN);

    init0_kernel<<<1, 32>>>();
    prep_kernel<<<12800, 256>>>(x, W1, Wg, bg, out);
    f1_kernel<<<16384, 128, SMEM_FFN>>>(b1, W2);
    f2_kernel<<<dim3(D_OUT / 128, N_TOK / 128, N_EXP), 128, SMEM_FFN>>>(b2, out);
}

// round 14
// speedup vs baseline: 1.0659x; 1.0561x over previous
#include <cuda_runtime.h>
#include <cuda_fp16.h>
#include <cstdint>

#define N_TOK 4096
#define D_IN  1024
#define D_HID 4096
#define D_OUT 1024
#define N_EXP 8

// ---------------- scratch (device globals; no runtime allocation) ----------------
__device__ __half g_Xh[(size_t)N_TOK * D_IN];            // x in fp16
__device__ __half g_W1h[(size_t)N_EXP * D_HID * D_IN];   // W1^T per expert: [e][N=4096][K=1024]
__device__ __half g_W2h[(size_t)N_EXP * D_OUT * D_HID];  // W2^T per expert: [e][N=1024][K=4096]
__device__ __half g_Hh[(size_t)N_TOK * 2 * D_HID];       // hidden acts fp16 per slot
__device__ float  g_topk_w[N_TOK * 2];
__device__ int    g_count[N_EXP];
__device__ int    g_slots[N_EXP * N_TOK];                // slot = 2*token + k

// ---------------- helpers ----------------
__device__ __forceinline__ uint32_t s2u(const void* p) {
    return (uint32_t)__cvta_generic_to_shared(p);
}
__device__ __forceinline__ void cpa16(uint32_t d, const void* g) {
    asm volatile("cp.async.cg.shared.global [%0], [%1], 16;\n" :: "r"(d), "l"(g));
}
#define LDSM_X4(r, a) \
    asm("ldmatrix.sync.aligned.m8n8.x4.shared.b16 {%0,%1,%2,%3}, [%4];" \
        : "=r"((r)[0]), "=r"((r)[1]), "=r"((r)[2]), "=r"((r)[3]) : "r"(a) : "memory")

__device__ __forceinline__ void mma_f16(float* d, const uint32_t* a, const uint32_t* b) {
    asm("mma.sync.aligned.m16n8k16.row.col.f32.f16.f16.f32 "
        "{%0,%1,%2,%3}, {%4,%5,%6,%7}, {%8,%9}, {%0,%1,%2,%3};"
        : "+f"(d[0]), "+f"(d[1]), "+f"(d[2]), "+f"(d[3])
        : "r"(a[0]), "r"(a[1]), "r"(a[2]), "r"(a[3]),
          "r"(b[0]), "r"(b[1]));
}
__device__ __forceinline__ void redadd(float* p, float v) {
    asm volatile("red.global.add.f32 [%0], %1;" :: "l"(p), "f"(v) : "memory");
}

// ---------------- init0: zero expert counters (must precede gating atomics) ----------------
__global__ void init0_kernel() {
    if (threadIdx.x < N_EXP) g_count[threadIdx.x] = 0;
}

// ============ shared device bodies ============

template <int K, int N>
__device__ __forceinline__ void transpose_tile_256(const float* __restrict__ S,
                                                   __half* __restrict__ D,
                                                   int n0, int k0, float (*t)[65], int tid) {
    const int tx = tid & 31, ty = tid >> 5;   // 32 x 8
#pragma unroll
    for (int j = 0; j < 64; j += 8) {
        t[ty + j][tx]      = S[(size_t)(k0 + ty + j) * N + n0 + tx];
        t[ty + j][tx + 32] = S[(size_t)(k0 + ty + j) * N + n0 + tx + 32];
    }
    __syncthreads();
#pragma unroll
    for (int p = 0; p < 2; p++) {
        int n = p * 32 + (tid >> 3);
        int m = tid & 7;
        float f[8];
#pragma unroll
        for (int i = 0; i < 8; i++) f[i] = t[8 * m + i][n];
        half2 hh[4];
        hh[0] = __floats2half2_rn(f[0], f[1]);
        hh[1] = __floats2half2_rn(f[2], f[3]);
        hh[2] = __floats2half2_rn(f[4], f[5]);
        hh[3] = __floats2half2_rn(f[6], f[7]);
        *(uint4*)(D + (size_t)(n0 + n) * K + k0 + 8 * m) = *(uint4*)hh;
    }
}

// 128-thread variant; caller loops tiles. Needs __syncthreads between reuses.
template <int K, int N>
__device__ __forceinline__ void transpose_tile_128(const float* __restrict__ S,
                                                   __half* __restrict__ D,
                                                   int n0, int k0, float (*t)[65], int tid) {
    const int tx = tid & 31, ty = tid >> 5;   // 32 x 4
#pragma unroll
    for (int j = 0; j < 64; j += 4) {
        t[ty + j][tx]      = S[(size_t)(k0 + ty + j) * N + n0 + tx];
        t[ty + j][tx + 32] = S[(size_t)(k0 + ty + j) * N + n0 + tx + 32];
    }
    __syncthreads();
#pragma unroll
    for (int p = 0; p < 4; p++) {
        int n = p * 16 + (tid >> 3);
        int m = tid & 7;
        float f[8];
#pragma unroll
        for (int i = 0; i < 8; i++) f[i] = t[8 * m + i][n];
        half2 hh[4];
        hh[0] = __floats2half2_rn(f[0], f[1]);
        hh[1] = __floats2half2_rn(f[2], f[3]);
        hh[2] = __floats2half2_rn(f[4], f[5]);
        hh[3] = __floats2half2_rn(f[6], f[7]);
        *(uint4*)(D + (size_t)(n0 + n) * K + k0 + 8 * m) = *(uint4*)hh;
    }
}

// ---------------- P1: fused ctW1 + gating(+x->fp16) + out-zero ----------------
__global__ void __launch_bounds__(256)
prep_kernel(const float* __restrict__ x,  const float* __restrict__ W1,
            const float* __restrict__ Wg, const float* __restrict__ bg,
            float* __restrict__ out) {
    __shared__ float t[64][65];
    const int bid = blockIdx.x;
    const int tid = threadIdx.x;

    if (bid < 8192) {                       // ---- transpose W1 tile ----
        const int e = bid >> 10, tile = bid & 1023;
        const int nt = tile >> 4, kt = tile & 15;
        transpose_tile_256<D_IN, D_HID>(W1 + (size_t)e * D_IN * D_HID,
                                        g_W1h + (size_t)e * D_HID * D_IN,
                                        nt * 64, kt * 64, t, tid);
        return;
    }
    if (bid >= 8704) {                      // ---- zero out ----
        int i = (bid - 8704) * 256 + tid;
        ((float4*)out)[i] = make_float4(0.f, 0.f, 0.f, 0.f);
        return;
    }

    // ---- gating + x->fp16 for 8 tokens ----
    const int tb   = (bid - 8192) * 8;
    const int tok  = tb + (tid >> 5);
    const int lane = tid & 31;
    {
        const float4* xv = (const float4*)(x + (size_t)tb * D_IN);
        half2* xo = (half2*)(g_Xh + (size_t)tb * D_IN);
#pragma unroll
        for (int i = tid; i < 8 * D_IN / 4; i += 256) {
            float4 v = xv[i];
            xo[2 * i]     = __floats2half2_rn(v.x, v.y);
            xo[2 * i + 1] = __floats2half2_rn(v.z, v.w);
        }
    }

    float acc[8];
#pragma unroll
    for (int e = 0; e < 8; e++) acc[e] = 0.f;
    const float* xr = x + (size_t)tok * D_IN;
    for (int d = lane; d < D_IN; d += 32) {
        float xv = xr[d];
        float4 w0 = *(const float4*)(Wg + d * 8);
        float4 w1 = *(const float4*)(Wg + d * 8 + 4);
        acc[0] += xv * w0.x; acc[1] += xv * w0.y;
        acc[2] += xv * w0.z; acc[3] += xv * w0.w;
        acc[4] += xv * w1.x; acc[5] += xv * w1.y;
        acc[6] += xv * w1.z; acc[7] += xv * w1.w;
    }
#pragma unroll
    for (int off = 16; off > 0; off >>= 1)
#pragma unroll
        for (int e = 0; e < 8; e++)
            acc[e] += __shfl_xor_sync(0xFFFFFFFFu, acc[e], off);

    if (lane == 0) {
        float l[8];
#pragma unroll
        for (int e = 0; e < 8; e++) l[e] = acc[e] + bg[e];
        float mx = l[0];
#pragma unroll
        for (int e = 1; e < 8; e++) mx = fmaxf(mx, l[e]);
        float p[8], s = 0.f;
#pragma unroll
        for (int e = 0; e < 8; e++) { p[e] = expf(l[e] - mx); s += p[e]; }
        float inv = 1.f / s;
#pragma unroll
        for (int e = 0; e < 8; e++) p[e] *= inv;

        int i0 = 0; float v0 = p[0];
#pragma unroll
        for (int e = 1; e < 8; e++) if (p[e] > v0) { v0 = p[e]; i0 = e; }
        int i1 = -1; float v1 = -1.f;
#pragma unroll
        for (int e = 0; e < 8; e++) if (e != i0 && p[e] > v1) { v1 = p[e]; i1 = e; }

        float e1 = expf(v1 - v0);
        float den = 1.f / (1.f + e1);
        int p0 = atomicAdd(&g_count[i0], 1);
        g_slots[i0 * N_TOK + p0] = 2 * tok;
        int p1 = atomicAdd(&g_count[i1], 1);
        g_slots[i1 * N_TOK + p1] = 2 * tok + 1;
        g_topk_w[2 * tok]     = den;
        g_topk_w[2 * tok + 1] = e1 * den;
    }
}

// ---------------- ffn GEMM body (R11 proven): 128x128x64 tile, 3-stage ring, 1 barrier/stage ----------------
template <bool FIRST>
__device__ __forceinline__ void ffn_body(int e, int m0, int n0,
                                         const float* __restrict__ Bias,
                                         float* __restrict__ out, char* smem) {
    constexpr int K  = FIRST ? D_IN : D_HID;
    constexpr int N  = FIRST ? D_HID : D_OUT;
    constexpr int BM = 128, BK = 64;
    constexpr int STRB = (BK + 8) * 2;     // 144 bytes/row
    constexpr int NS = K / BK;
    constexpr int ASTG = BM * STRB;        // 18432 B per stage

    constexpr int OFF_SLOT = 0;
    constexpr int OFF_A    = 1024;                 // 3 stages
    constexpr int OFF_B    = 1024 + 3 * ASTG;      // 3 stages

    const uint32_t su = s2u(smem);
    const int cnt = g_count[e];
    const int rows = min(BM, cnt - m0);

    const int tid  = threadIdx.x;
    const int lane = tid & 31;
    const int warp = tid >> 5;
    const int gid  = lane >> 2;
    const int itg  = lane & 3;
    const int wm = warp >> 1;
    const int wn = warp & 1;

    int* sSlot = (int*)(smem + OFF_SLOT);
    sSlot[tid] = g_slots[e * N_TOK + m0 + ((tid < rows) ? tid : 0)];
    __syncthreads();

    const __half* Wb = (FIRST ? g_W1h : g_W2h)
                     + (size_t)e * (size_t)N * K + (size_t)n0 * K;

    auto stage = [&](int s) {
        const int k0 = s * BK;
        const int sl = s % 3;
        const uint32_t ab = su + OFF_A + sl * ASTG;
        const uint32_t bb = su + OFF_B + sl * ASTG;
#pragma unroll
        for (int it = 0; it < 8; it++) {
            int idx = it * 128 + tid;
            int row = idx >> 3, c = idx & 7;
            int slot = sSlot[row];
            const __half* g = FIRST
                ? g_Xh + (size_t)(slot >> 1) * D_IN  + k0 + c * 8
                : g_Hh + (size_t)slot        * D_HID + k0 + c * 8;
            cpa16(ab + row * STRB + c * 16, g);
        }
#pragma unroll
        for (int it = 0; it < 8; it++) {
            int idx = it * 128 + tid;
            int row = idx >> 3, c = idx & 7;
            cpa16(bb + row * STRB + c * 16, Wb + (size_t)row * K + k0 + c * 8);
        }
        asm volatile("cp.async.commit_group;\n");
    };

    float acc[4][8][4];
#pragma unroll
    for (int a = 0; a < 4; a++)
#pragma unroll
        for (int b = 0; b < 8; b++)
#pragma unroll
            for (int c = 0; c < 4; c++) acc[a][b][c] = 0.f;

    const uint32_t aLane = (uint32_t)((wm * 64 + (lane & 15)) * STRB + (lane >> 4) * 16);
    const uint32_t bLane = (uint32_t)((wn * 64 + (lane & 7) + ((lane & 16) ? 8 : 0)) * STRB
                                      + ((lane & 8) ? 16 : 0));

    stage(0);
    stage(1);
    for (int s = 0; s < NS; ++s) {
        if (s + 1 < NS) {
            asm volatile("cp.async.wait_group 1;\n");
        } else {
            asm volatile("cp.async.wait_group 0;\n");
        }
        __syncthreads();
        if (s + 2 < NS) stage(s + 2);

        const int sl = s % 3;
        const uint32_t aS = su + OFF_A + sl * ASTG + aLane;
        const uint32_t bS = su + OFF_B + sl * ASTG + bLane;

        uint32_t af[2][4][4], bf[2][4][4];
#pragma unroll
        for (int mf = 0; mf < 4; ++mf) LDSM_X4(af[0][mf], aS + mf * 16 * STRB);
#pragma unroll
        for (int p = 0; p < 4; ++p)    LDSM_X4(bf[0][p],  bS + p * 16 * STRB);

#pragma unroll
        for (int ks = 0; ks < BK / 16; ++ks) {
            const int cur = ks & 1, nxt = cur ^ 1;
            if (ks + 1 < BK / 16) {
#pragma unroll
                for (int mf = 0; mf < 4; ++mf)
                    LDSM_X4(af[nxt][mf], aS + (ks + 1) * 32 + mf * 16 * STRB);
#pragma unroll
                for (int p = 0; p < 4; ++p)
                    LDSM_X4(bf[nxt][p],  bS + (ks + 1) * 32 + p * 16 * STRB);
            }
#pragma unroll
            for (int mf = 0; mf < 4; ++mf)
#pragma unroll
                for (int p = 0; p < 4; ++p) {
                    mma_f16(acc[mf][2 * p],     af[cur][mf], &bf[cur][p][0]);
                    mma_f16(acc[mf][2 * p + 1], af[cur][mf], &bf[cur][p][2]);
                }
        }
    }

#pragma unroll
    for (int mf = 0; mf < 4; ++mf) {
        int rl = wm * 64 + mf * 16 + gid;
#pragma unroll
        for (int nf = 0; nf < 8; ++nf) {
            int n = n0 + wn * 64 + nf * 8 + 2 * itg;
            float2 bv = *(const float2*)(Bias + (size_t)e * N + n);
            float v00 = acc[mf][nf][0] + bv.x;
            float v01 = acc[mf][nf][1] + bv.y;
            float v10 = acc[mf][nf][2] + bv.x;
            float v11 = acc[mf][nf][3] + bv.y;
            if (FIRST) {
                v00 = fmaxf(v00, 0.f); v01 = fmaxf(v01, 0.f);
                v10 = fmaxf(v10, 0.f); v11 = fmaxf(v11, 0.f);
                if (rl < rows) {
                    int slot = sSlot[rl];
                    *(half2*)(g_Hh + (size_t)slot * D_HID + n) = __floats2half2_rn(v00, v01);
                }
                if (rl + 8 < rows) {
                    int slot = sSlot[rl + 8];
                    *(half2*)(g_Hh + (size_t)slot * D_HID + n) = __floats2half2_rn(v10, v11);
                }
            } else {
                if (rl < rows) {
                    int slot = sSlot[rl];
                    float w = g_topk_w[slot];
                    float* o = out + (size_t)(slot >> 1) * D_OUT + n;
                    redadd(o,     v00 * w);
                    redadd(o + 1, v01 * w);
                }
                if (rl + 8 < rows) {
                    int slot = sSlot[rl + 8];
                    float w = g_topk_w[slot];
                    float* o = out + (size_t)(slot >> 1) * D_OUT + n;
                    redadd(o,     v10 * w);
                    redadd(o + 1, v11 * w);
                }
            }
        }
    }
}

// ---------------- F1: ffn layer 1 + batched ctW2 (4 GEMM tiles : 1 ctW2 CTA of 4 tiles) ----------------
__global__ void __launch_bounds__(128, 2)
f1_kernel(const float* __restrict__ b1, const float* __restrict__ W2) {
    extern __shared__ __align__(128) char smem[];
    const int bid = blockIdx.x;
    const int i = bid / 5, r = bid % 5;
    if (r < 4) {
        // f1 GEMM tile j in [0,8192)
        const int j = i * 4 + r;
        const int nt = j & 31, mt = (j >> 5) & 31, e = j >> 10;
        if (mt * 128 >= g_count[e]) return;
        ffn_body<true>(e, mt * 128, nt * 128, b1, nullptr, smem);
    } else {
        // ctW2 batch i in [0,2048): 4 consecutive tiles (same k-rows, adjacent n-cols)
        float (*t)[65] = (float(*)[65])smem;
#pragma unroll
        for (int q = 0; q < 4; q++) {
            const int tl = i * 4 + q;
            const int e = tl >> 10, tile = tl & 1023;
            const int nt = tile & 15, kt = tile >> 4;
            if (q) __syncthreads();   // smem reuse
            transpose_tile_128<D_HID, D_OUT>(W2 + (size_t)e * D_HID * D_OUT,
                                             g_W2h + (size_t)e * D_OUT * D_HID,
                                             nt * 64, kt * 64, t, threadIdx.x);
        }
    }
}

// ---------------- F2: ffn layer 2 (+fused combine via red.add) ----------------
__global__ void __launch_bounds__(128, 2)
f2_kernel(const float* __restrict__ b2, float* __restrict__ out) {
    extern __shared__ __align__(128) char smem[];
    const int e = blockIdx.z, mt = blockIdx.y, nt = blockIdx.x;
    if (mt * 128 >= g_count[e]) return;
    ffn_body<false>(e, mt * 128, nt * 128, b2, out, smem);
}

// ---------------- launch ----------------
extern "C" void kernel_launch(void* const* d_in, const int* in_sizes, int n_in,
                              void* d_out, int out_size) {
    const float* x  = (const float*)d_in[0];
    const float* W1 = (const float*)d_in[1];
    const float* b1 = (const float*)d_in[2];
    const float* W2 = (const float*)d_in[3];
    const float* b2 = (const float*)d_in[4];
    const float* Wg = (const float*)d_in[5];
    const float* bg = (const float*)d_in[6];
    float* out = (float*)d_out;

    constexpr int SMEM_FFN = 1024 + 6 * 128 * 144;   // 111616 -> 2 CTAs/SM
    cudaFuncSetAttribute(f1_kernel, cudaFuncAttributeMaxDynamicSharedMemorySize, SMEM_FFN);
    cudaFuncSetAttribute(f2_kernel, cudaFuncAttributeMaxDynamicSharedMemorySize, SMEM_FFN);

    init0_kernel<<<1, 32>>>();
    prep_kernel<<<12800, 256>>>(x, W1, Wg, bg, out);
    f1_kernel<<<2048 * 5, 128, SMEM_FFN>>>(b1, W2);   // 8192 GEMM tiles + 2048 ctW2 batches
    f2_kernel<<<dim3(D_OUT / 128, N_TOK / 128, N_EXP), 128, SMEM_FFN>>>(b2, out);
}

// round 15
// speedup vs baseline: 1.0739x; 1.0075x over previous
#include <cuda_runtime.h>
#include <cuda_fp16.h>
#include <cstdint>

#define N_TOK 4096
#define D_IN  1024
#define D_HID 4096
#define D_OUT 1024
#define N_EXP 8

// ---------------- scratch (device globals; no runtime allocation) ----------------
__device__ __half g_Xh[(size_t)N_TOK * D_IN];            // x in fp16
__device__ __half g_W1h[(size_t)N_EXP * D_HID * D_IN];   // W1^T per expert: [e][N=4096][K=1024]
__device__ __half g_W2h[(size_t)N_EXP * D_OUT * D_HID];  // W2^T per expert: [e][N=1024][K=4096]
__device__ __half g_Hh[(size_t)N_TOK * 2 * D_HID];       // hidden acts fp16 per slot
__device__ float  g_topk_w[N_TOK * 2];
__device__ int    g_count[N_EXP];
__device__ int    g_slots[N_EXP * N_TOK];                // slot = 2*token + k

// ---------------- helpers ----------------
__device__ __forceinline__ uint32_t s2u(const void* p) {
    return (uint32_t)__cvta_generic_to_shared(p);
}
__device__ __forceinline__ void cpa16(uint32_t d, const void* g) {
    asm volatile("cp.async.cg.shared.global [%0], [%1], 16;\n" :: "r"(d), "l"(g));
}
#define LDSM_X4(r, a) \
    asm("ldmatrix.sync.aligned.m8n8.x4.shared.b16 {%0,%1,%2,%3}, [%4];" \
        : "=r"((r)[0]), "=r"((r)[1]), "=r"((r)[2]), "=r"((r)[3]) : "r"(a) : "memory")

__device__ __forceinline__ void mma_f16(float* d, const uint32_t* a, const uint32_t* b) {
    asm("mma.sync.aligned.m16n8k16.row.col.f32.f16.f16.f32 "
        "{%0,%1,%2,%3}, {%4,%5,%6,%7}, {%8,%9}, {%0,%1,%2,%3};"
        : "+f"(d[0]), "+f"(d[1]), "+f"(d[2]), "+f"(d[3])
        : "r"(a[0]), "r"(a[1]), "r"(a[2]), "r"(a[3]),
          "r"(b[0]), "r"(b[1]));
}
__device__ __forceinline__ void redadd(float* p, float v) {
    asm volatile("red.global.add.f32 [%0], %1;" :: "l"(p), "f"(v) : "memory");
}

// ---------------- init0: zero expert counters (must precede gating atomics) ----------------
__global__ void init0_kernel() {
    if (threadIdx.x < N_EXP) g_count[threadIdx.x] = 0;
}

// ============ shared device bodies ============

// transpose one 64x64 tile, 256 threads (sync between reuses handled by caller)
template <int K, int N>
__device__ __forceinline__ void transpose_tile_256(const float* __restrict__ S,
                                                   __half* __restrict__ D,
                                                   int n0, int k0, float (*t)[65], int tid) {
    const int tx = tid & 31, ty = tid >> 5;   // 32 x 8
#pragma unroll
    for (int j = 0; j < 64; j += 8) {
        t[ty + j][tx]      = S[(size_t)(k0 + ty + j) * N + n0 + tx];
        t[ty + j][tx + 32] = S[(size_t)(k0 + ty + j) * N + n0 + tx + 32];
    }
    __syncthreads();
#pragma unroll
    for (int p = 0; p < 2; p++) {
        int n = p * 32 + (tid >> 3);
        int m = tid & 7;
        float f[8];
#pragma unroll
        for (int i = 0; i < 8; i++) f[i] = t[8 * m + i][n];
        half2 hh[4];
        hh[0] = __floats2half2_rn(f[0], f[1]);
        hh[1] = __floats2half2_rn(f[2], f[3]);
        hh[2] = __floats2half2_rn(f[4], f[5]);
        hh[3] = __floats2half2_rn(f[6], f[7]);
        *(uint4*)(D + (size_t)(n0 + n) * K + k0 + 8 * m) = *(uint4*)hh;
    }
}

// 128-thread variant; caller loops tiles with __syncthreads between reuses.
template <int K, int N>
__device__ __forceinline__ void transpose_tile_128(const float* __restrict__ S,
                                                   __half* __restrict__ D,
                                                   int n0, int k0, float (*t)[65], int tid) {
    const int tx = tid & 31, ty = tid >> 5;   // 32 x 4
#pragma unroll
    for (int j = 0; j < 64; j += 4) {
        t[ty + j][tx]      = S[(size_t)(k0 + ty + j) * N + n0 + tx];
        t[ty + j][tx + 32] = S[(size_t)(k0 + ty + j) * N + n0 + tx + 32];
    }
    __syncthreads();
#pragma unroll
    for (int p = 0; p < 4; p++) {
        int n = p * 16 + (tid >> 3);
        int m = tid & 7;
        float f[8];
#pragma unroll
        for (int i = 0; i < 8; i++) f[i] = t[8 * m + i][n];
        half2 hh[4];
        hh[0] = __floats2half2_rn(f[0], f[1]);
        hh[1] = __floats2half2_rn(f[2], f[3]);
        hh[2] = __floats2half2_rn(f[4], f[5]);
        hh[3] = __floats2half2_rn(f[6], f[7]);
        *(uint4*)(D + (size_t)(n0 + n) * K + k0 + 8 * m) = *(uint4*)hh;
    }
}

// ---------------- P1: fused batched-ctW1 + gating(+x->fp16) ----------------
// grid: [0,2048) ctW1 batches (4 consecutive k-tiles each), [2048,2560) gating (8 tokens each)
__global__ void __launch_bounds__(256)
prep_kernel(const float* __restrict__ x,  const float* __restrict__ W1,
            const float* __restrict__ Wg, const float* __restrict__ bg) {
    __shared__ float t[64][65];
    const int bid = blockIdx.x;
    const int tid = threadIdx.x;

    if (bid < 2048) {                       // ---- transpose W1: 4 tiles per CTA ----
#pragma unroll
        for (int q = 0; q < 4; q++) {
            const int tl = bid * 4 + q;                 // tile index in [0,8192)
            const int e = tl >> 10, tile = tl & 1023;
            const int nt = tile >> 4, kt = tile & 15;   // consecutive tl -> same nt, adjacent kt
            if (q) __syncthreads();                     // smem reuse
            transpose_tile_256<D_IN, D_HID>(W1 + (size_t)e * D_IN * D_HID,
                                            g_W1h + (size_t)e * D_HID * D_IN,
                                            nt * 64, kt * 64, t, tid);
        }
        return;
    }

    // ---- gating + x->fp16 for 8 tokens ----
    const int tb   = (bid - 2048) * 8;
    const int tok  = tb + (tid >> 5);
    const int lane = tid & 31;
    {
        const float4* xv = (const float4*)(x + (size_t)tb * D_IN);
        half2* xo = (half2*)(g_Xh + (size_t)tb * D_IN);
#pragma unroll
        for (int i = tid; i < 8 * D_IN / 4; i += 256) {
            float4 v = xv[i];
            xo[2 * i]     = __floats2half2_rn(v.x, v.y);
            xo[2 * i + 1] = __floats2half2_rn(v.z, v.w);
        }
    }

    float acc[8];
#pragma unroll
    for (int e = 0; e < 8; e++) acc[e] = 0.f;
    const float* xr = x + (size_t)tok * D_IN;
    for (int d = lane; d < D_IN; d += 32) {
        float xv = xr[d];
        float4 w0 = *(const float4*)(Wg + d * 8);
        float4 w1 = *(const float4*)(Wg + d * 8 + 4);
        acc[0] += xv * w0.x; acc[1] += xv * w0.y;
        acc[2] += xv * w0.z; acc[3] += xv * w0.w;
        acc[4] += xv * w1.x; acc[5] += xv * w1.y;
        acc[6] += xv * w1.z; acc[7] += xv * w1.w;
    }
#pragma unroll
    for (int off = 16; off > 0; off >>= 1)
#pragma unroll
        for (int e = 0; e < 8; e++)
            acc[e] += __shfl_xor_sync(0xFFFFFFFFu, acc[e], off);

    if (lane == 0) {
        float l[8];
#pragma unroll
        for (int e = 0; e < 8; e++) l[e] = acc[e] + bg[e];
        float mx = l[0];
#pragma unroll
        for (int e = 1; e < 8; e++) mx = fmaxf(mx, l[e]);
        float p[8], s = 0.f;
#pragma unroll
        for (int e = 0; e < 8; e++) { p[e] = expf(l[e] - mx); s += p[e]; }
        float inv = 1.f / s;
#pragma unroll
        for (int e = 0; e < 8; e++) p[e] *= inv;

        int i0 = 0; float v0 = p[0];
#pragma unroll
        for (int e = 1; e < 8; e++) if (p[e] > v0) { v0 = p[e]; i0 = e; }
        int i1 = -1; float v1 = -1.f;
#pragma unroll
        for (int e = 0; e < 8; e++) if (e != i0 && p[e] > v1) { v1 = p[e]; i1 = e; }

        float e1 = expf(v1 - v0);
        float den = 1.f / (1.f + e1);
        int p0 = atomicAdd(&g_count[i0], 1);
        g_slots[i0 * N_TOK + p0] = 2 * tok;
        int p1 = atomicAdd(&g_count[i1], 1);
        g_slots[i1 * N_TOK + p1] = 2 * tok + 1;
        g_topk_w[2 * tok]     = den;
        g_topk_w[2 * tok + 1] = e1 * den;
    }
}

// ---------------- ffn GEMM body (R11/R14 proven): 128x128x64 tile, 3-stage ring ----------------
template <bool FIRST>
__device__ __forceinline__ void ffn_body(int e, int m0, int n0,
                                         const float* __restrict__ Bias,
                                         float* __restrict__ out, char* smem) {
    constexpr int K  = FIRST ? D_IN : D_HID;
    constexpr int N  = FIRST ? D_HID : D_OUT;
    constexpr int BM = 128, BK = 64;
    constexpr int STRB = (BK + 8) * 2;     // 144 bytes/row
    constexpr int NS = K / BK;
    constexpr int ASTG = BM * STRB;        // 18432 B per stage

    constexpr int OFF_SLOT = 0;
    constexpr int OFF_A    = 1024;                 // 3 stages
    constexpr int OFF_B    = 1024 + 3 * ASTG;      // 3 stages

    const uint32_t su = s2u(smem);
    const int cnt = g_count[e];
    const int rows = min(BM, cnt - m0);

    const int tid  = threadIdx.x;
    const int lane = tid & 31;
    const int warp = tid >> 5;
    const int gid  = lane >> 2;
    const int itg  = lane & 3;
    const int wm = warp >> 1;
    const int wn = warp & 1;

    int* sSlot = (int*)(smem + OFF_SLOT);
    sSlot[tid] = g_slots[e * N_TOK + m0 + ((tid < rows) ? tid : 0)];
    __syncthreads();

    const __half* Wb = (FIRST ? g_W1h : g_W2h)
                     + (size_t)e * (size_t)N * K + (size_t)n0 * K;

    auto stage = [&](int s) {
        const int k0 = s * BK;
        const int sl = s % 3;
        const uint32_t ab = su + OFF_A + sl * ASTG;
        const uint32_t bb = su + OFF_B + sl * ASTG;
#pragma unroll
        for (int it = 0; it < 8; it++) {
            int idx = it * 128 + tid;
            int row = idx >> 3, c = idx & 7;
            int slot = sSlot[row];
            const __half* g = FIRST
                ? g_Xh + (size_t)(slot >> 1) * D_IN  + k0 + c * 8
                : g_Hh + (size_t)slot        * D_HID + k0 + c * 8;
            cpa16(ab + row * STRB + c * 16, g);
        }
#pragma unroll
        for (int it = 0; it < 8; it++) {
            int idx = it * 128 + tid;
            int row = idx >> 3, c = idx & 7;
            cpa16(bb + row * STRB + c * 16, Wb + (size_t)row * K + k0 + c * 8);
        }
        asm volatile("cp.async.commit_group;\n");
    };

    float acc[4][8][4];
#pragma unroll
    for (int a = 0; a < 4; a++)
#pragma unroll
        for (int b = 0; b < 8; b++)
#pragma unroll
            for (int c = 0; c < 4; c++) acc[a][b][c] = 0.f;

    const uint32_t aLane = (uint32_t)((wm * 64 + (lane & 15)) * STRB + (lane >> 4) * 16);
    const uint32_t bLane = (uint32_t)((wn * 64 + (lane & 7) + ((lane & 16) ? 8 : 0)) * STRB
                                      + ((lane & 8) ? 16 : 0));

    stage(0);
    stage(1);
    for (int s = 0; s < NS; ++s) {
        if (s + 1 < NS) {
            asm volatile("cp.async.wait_group 1;\n");
        } else {
            asm volatile("cp.async.wait_group 0;\n");
        }
        __syncthreads();
        if (s + 2 < NS) stage(s + 2);

        const int sl = s % 3;
        const uint32_t aS = su + OFF_A + sl * ASTG + aLane;
        const uint32_t bS = su + OFF_B + sl * ASTG + bLane;

        uint32_t af[2][4][4], bf[2][4][4];
#pragma unroll
        for (int mf = 0; mf < 4; ++mf) LDSM_X4(af[0][mf], aS + mf * 16 * STRB);
#pragma unroll
        for (int p = 0; p < 4; ++p)    LDSM_X4(bf[0][p],  bS + p * 16 * STRB);

#pragma unroll
        for (int ks = 0; ks < BK / 16; ++ks) {
            const int cur = ks & 1, nxt = cur ^ 1;
            if (ks + 1 < BK / 16) {
#pragma unroll
                for (int mf = 0; mf < 4; ++mf)
                    LDSM_X4(af[nxt][mf], aS + (ks + 1) * 32 + mf * 16 * STRB);
#pragma unroll
                for (int p = 0; p < 4; ++p)
                    LDSM_X4(bf[nxt][p],  bS + (ks + 1) * 32 + p * 16 * STRB);
            }
#pragma unroll
            for (int mf = 0; mf < 4; ++mf)
#pragma unroll
                for (int p = 0; p < 4; ++p) {
                    mma_f16(acc[mf][2 * p],     af[cur][mf], &bf[cur][p][0]);
                    mma_f16(acc[mf][2 * p + 1], af[cur][mf], &bf[cur][p][2]);
                }
        }
    }

#pragma unroll
    for (int mf = 0; mf < 4; ++mf) {
        int rl = wm * 64 + mf * 16 + gid;
#pragma unroll
        for (int nf = 0; nf < 8; ++nf) {
            int n = n0 + wn * 64 + nf * 8 + 2 * itg;
            float2 bv = *(const float2*)(Bias + (size_t)e * N + n);
            float v00 = acc[mf][nf][0] + bv.x;
            float v01 = acc[mf][nf][1] + bv.y;
            float v10 = acc[mf][nf][2] + bv.x;
            float v11 = acc[mf][nf][3] + bv.y;
            if (FIRST) {
                v00 = fmaxf(v00, 0.f); v01 = fmaxf(v01, 0.f);
                v10 = fmaxf(v10, 0.f); v11 = fmaxf(v11, 0.f);
                if (rl < rows) {
                    int slot = sSlot[rl];
                    *(half2*)(g_Hh + (size_t)slot * D_HID + n) = __floats2half2_rn(v00, v01);
                }
                if (rl + 8 < rows) {
                    int slot = sSlot[rl + 8];
                    *(half2*)(g_Hh + (size_t)slot * D_HID + n) = __floats2half2_rn(v10, v11);
                }
            } else {
                if (rl < rows) {
                    int slot = sSlot[rl];
                    float w = g_topk_w[slot];
                    float* o = out + (size_t)(slot >> 1) * D_OUT + n;
                    redadd(o,     v00 * w);
                    redadd(o + 1, v01 * w);
                }
                if (rl + 8 < rows) {
                    int slot = sSlot[rl + 8];
                    float w = g_topk_w[slot];
                    float* o = out + (size_t)(slot >> 1) * D_OUT + n;
                    redadd(o,     v10 * w);
                    redadd(o + 1, v11 * w);
                }
            }
        }
    }
}

// ---------------- F1: ffn layer 1 + batched ctW2 + out-zeroing ----------------
// bids [0,10240): 4 GEMM tiles : 1 ctW2 batch (bid%5). bids [10240,12288): zero out.
__global__ void __launch_bounds__(128, 2)
f1_kernel(const float* __restrict__ b1, const float* __restrict__ W2,
          float* __restrict__ out) {
    extern __shared__ __align__(128) char smem[];
    const int bid = blockIdx.x;
    if (bid >= 10240) {                     // ---- zero out (consumed only by f2's red.add) ----
        const int z = bid - 10240;          // 2048 blocks x 128 thr x 4 float4 = 4M floats
        float4* o = (float4*)out + (size_t)z * 512 + threadIdx.x;
#pragma unroll
        for (int q = 0; q < 4; q++) o[q * 128] = make_float4(0.f, 0.f, 0.f, 0.f);
        return;
    }
    const int i = bid / 5, r = bid % 5;
    if (r < 4) {
        const int j = i * 4 + r;            // f1 GEMM tile in [0,8192)
        const int nt = j & 31, mt = (j >> 5) & 31, e = j >> 10;
        if (mt * 128 >= g_count[e]) return;
        ffn_body<true>(e, mt * 128, nt * 128, b1, nullptr, smem);
    } else {
        float (*t)[65] = (float(*)[65])smem;
#pragma unroll
        for (int q = 0; q < 4; q++) {       // ctW2 batch: 4 consecutive tiles
            const int tl = i * 4 + q;
            const int e = tl >> 10, tile = tl & 1023;
            const int nt = tile & 15, kt = tile >> 4;
            if (q) __syncthreads();
            transpose_tile_128<D_HID, D_OUT>(W2 + (size_t)e * D_HID * D_OUT,
                                             g_W2h + (size_t)e * D_OUT * D_HID,
                                             nt * 64, kt * 64, t, threadIdx.x);
        }
    }
}

// ---------------- F2: ffn layer 2 (+fused combine via red.add) ----------------
__global__ void __launch_bounds__(128, 2)
f2_kernel(const float* __restrict__ b2, float* __restrict__ out) {
    extern __shared__ __align__(128) char smem[];
    const int e = blockIdx.z, mt = blockIdx.y, nt = blockIdx.x;
    if (mt * 128 >= g_count[e]) return;
    ffn_body<false>(e, mt * 128, nt * 128, b2, out, smem);
}

// ---------------- launch ----------------
extern "C" void kernel_launch(void* const* d_in, const int* in_sizes, int n_in,
                              void* d_out, int out_size) {
    const float* x  = (const float*)d_in[0];
    const float* W1 = (const float*)d_in[1];
    const float* b1 = (const float*)d_in[2];
    const float* W2 = (const float*)d_in[3];
    const float* b2 = (const float*)d_in[4];
    const float* Wg = (const float*)d_in[5];
    const float* bg = (const float*)d_in[6];
    float* out = (float*)d_out;

    constexpr int SMEM_FFN = 1024 + 6 * 128 * 144;   // 111616 -> 2 CTAs/SM
    cudaFuncSetAttribute(f1_kernel, cudaFuncAttributeMaxDynamicSharedMemorySize, SMEM_FFN);
    cudaFuncSetAttribute(f2_kernel, cudaFuncAttributeMaxDynamicSharedMemorySize, SMEM_FFN);

    init0_kernel<<<1, 32>>>();
    prep_kernel<<<2560, 256>>>(x, W1, Wg, bg);       // 2048 ctW1 batches + 512 gating
    f1_kernel<<<10240 + 2048, 128, SMEM_FFN>>>(b1, W2, out);
    f2_kernel<<<dim3(D_OUT / 128, N_TOK / 128, N_EXP), 128, SMEM_FFN>>>(b2, out);
}

// round 16
// speedup vs baseline: 1.0789x; 1.0047x over previous
#include <cuda_runtime.h>
#include <cuda_fp16.h>
#include <cstdint>

#define N_TOK 4096
#define D_IN  1024
#define D_HID 4096
#define D_OUT 1024
#define N_EXP 8

// ---------------- scratch (device globals; no runtime allocation) ----------------
__device__ __half g_Xh[(size_t)N_TOK * D_IN];            // x in fp16
__device__ __half g_W1h[(size_t)N_EXP * D_HID * D_IN];   // W1^T per expert: [e][N=4096][K=1024]
__device__ __half g_W2h[(size_t)N_EXP * D_OUT * D_HID];  // W2^T per expert: [e][N=1024][K=4096]
__device__ __half g_Hh[(size_t)N_TOK * 2 * D_HID];       // hidden acts fp16 per slot
__device__ float  g_topk_w[N_TOK * 2];
__device__ int    g_count[N_EXP];
__device__ int    g_slots[N_EXP * N_TOK];                // slot = 2*token + k

// ---------------- helpers ----------------
__device__ __forceinline__ uint32_t s2u(const void* p) {
    return (uint32_t)__cvta_generic_to_shared(p);
}
__device__ __forceinline__ void cpa16(uint32_t d, const void* g) {
    asm volatile("cp.async.cg.shared.global [%0], [%1], 16;\n" :: "r"(d), "l"(g));
}
#define LDSM_X4(r, a) \
    asm("ldmatrix.sync.aligned.m8n8.x4.shared.b16 {%0,%1,%2,%3}, [%4];" \
        : "=r"((r)[0]), "=r"((r)[1]), "=r"((r)[2]), "=r"((r)[3]) : "r"(a) : "memory")

__device__ __forceinline__ void mma_f16(float* d, const uint32_t* a, const uint32_t* b) {
    asm("mma.sync.aligned.m16n8k16.row.col.f32.f16.f16.f32 "
        "{%0,%1,%2,%3}, {%4,%5,%6,%7}, {%8,%9}, {%0,%1,%2,%3};"
        : "+f"(d[0]), "+f"(d[1]), "+f"(d[2]), "+f"(d[3])
        : "r"(a[0]), "r"(a[1]), "r"(a[2]), "r"(a[3]),
          "r"(b[0]), "r"(b[1]));
}
__device__ __forceinline__ void redadd(float* p, float v) {
    asm volatile("red.global.add.f32 [%0], %1;" :: "l"(p), "f"(v) : "memory");
}

// ---------------- init0: zero expert counters (must precede gating atomics) ----------------
__global__ void init0_kernel() {
    if (threadIdx.x < N_EXP) g_count[threadIdx.x] = 0;
}

// ============ shared device bodies ============

// transpose one 64x64 tile, 256 threads (sync between reuses handled by caller)
template <int K, int N>
__device__ __forceinline__ void transpose_tile_256(const float* __restrict__ S,
                                                   __half* __restrict__ D,
                                                   int n0, int k0, float (*t)[65], int tid) {
    const int tx = tid & 31, ty = tid >> 5;   // 32 x 8
#pragma unroll
    for (int j = 0; j < 64; j += 8) {
        t[ty + j][tx]      = S[(size_t)(k0 + ty + j) * N + n0 + tx];
        t[ty + j][tx + 32] = S[(size_t)(k0 + ty + j) * N + n0 + tx + 32];
    }
    __syncthreads();
#pragma unroll
    for (int p = 0; p < 2; p++) {
        int n = p * 32 + (tid >> 3);
        int m = tid & 7;
        float f[8];
#pragma unroll
        for (int i = 0; i < 8; i++) f[i] = t[8 * m + i][n];
        half2 hh[4];
        hh[0] = __floats2half2_rn(f[0], f[1]);
        hh[1] = __floats2half2_rn(f[2], f[3]);
        hh[2] = __floats2half2_rn(f[4], f[5]);
        hh[3] = __floats2half2_rn(f[6], f[7]);
        *(uint4*)(D + (size_t)(n0 + n) * K + k0 + 8 * m) = *(uint4*)hh;
    }
}

// 128-thread variant; caller loops tiles with __syncthreads between reuses.
template <int K, int N>
__device__ __forceinline__ void transpose_tile_128(const float* __restrict__ S,
                                                   __half* __restrict__ D,
                                                   int n0, int k0, float (*t)[65], int tid) {
    const int tx = tid & 31, ty = tid >> 5;   // 32 x 4
#pragma unroll
    for (int j = 0; j < 64; j += 4) {
        t[ty + j][tx]      = S[(size_t)(k0 + ty + j) * N + n0 + tx];
        t[ty + j][tx + 32] = S[(size_t)(k0 + ty + j) * N + n0 + tx + 32];
    }
    __syncthreads();
#pragma unroll
    for (int p = 0; p < 4; p++) {
        int n = p * 16 + (tid >> 3);
        int m = tid & 7;
        float f[8];
#pragma unroll
        for (int i = 0; i < 8; i++) f[i] = t[8 * m + i][n];
        half2 hh[4];
        hh[0] = __floats2half2_rn(f[0], f[1]);
        hh[1] = __floats2half2_rn(f[2], f[3]);
        hh[2] = __floats2half2_rn(f[4], f[5]);
        hh[3] = __floats2half2_rn(f[6], f[7]);
        *(uint4*)(D + (size_t)(n0 + n) * K + k0 + 8 * m) = *(uint4*)hh;
    }
}

// ---------------- P1: fused batched-ctW1 + gating(+x->fp16) ----------------
// grid: [0,2048) ctW1 batches (4 consecutive k-tiles each), [2048,2560) gating (8 tokens each)
__global__ void __launch_bounds__(256)
prep_kernel(const float* __restrict__ x,  const float* __restrict__ W1,
            const float* __restrict__ Wg, const float* __restrict__ bg) {
    __shared__ float t[64][65];
    const int bid = blockIdx.x;
    const int tid = threadIdx.x;

    if (bid < 2048) {                       // ---- transpose W1: 4 tiles per CTA ----
#pragma unroll
        for (int q = 0; q < 4; q++) {
            const int tl = bid * 4 + q;                 // tile index in [0,8192)
            const int e = tl >> 10, tile = tl & 1023;
            const int nt = tile >> 4, kt = tile & 15;
            if (q) __syncthreads();                     // smem reuse
            transpose_tile_256<D_IN, D_HID>(W1 + (size_t)e * D_IN * D_HID,
                                            g_W1h + (size_t)e * D_HID * D_IN,
                                            nt * 64, kt * 64, t, tid);
        }
        return;
    }

    // ---- gating + x->fp16 for 8 tokens ----
    const int tb   = (bid - 2048) * 8;
    const int tok  = tb + (tid >> 5);
    const int lane = tid & 31;
    {
        const float4* xv = (const float4*)(x + (size_t)tb * D_IN);
        half2* xo = (half2*)(g_Xh + (size_t)tb * D_IN);
#pragma unroll
        for (int i = tid; i < 8 * D_IN / 4; i += 256) {
            float4 v = xv[i];
            xo[2 * i]     = __floats2half2_rn(v.x, v.y);
            xo[2 * i + 1] = __floats2half2_rn(v.z, v.w);
        }
    }

    float acc[8];
#pragma unroll
    for (int e = 0; e < 8; e++) acc[e] = 0.f;
    const float* xr = x + (size_t)tok * D_IN;
    for (int d = lane; d < D_IN; d += 32) {
        float xv = xr[d];
        float4 w0 = *(const float4*)(Wg + d * 8);
        float4 w1 = *(const float4*)(Wg + d * 8 + 4);
        acc[0] += xv * w0.x; acc[1] += xv * w0.y;
        acc[2] += xv * w0.z; acc[3] += xv * w0.w;
        acc[4] += xv * w1.x; acc[5] += xv * w1.y;
        acc[6] += xv * w1.z; acc[7] += xv * w1.w;
    }
#pragma unroll
    for (int off = 16; off > 0; off >>= 1)
#pragma unroll
        for (int e = 0; e < 8; e++)
            acc[e] += __shfl_xor_sync(0xFFFFFFFFu, acc[e], off);

    if (lane == 0) {
        float l[8];
#pragma unroll
        for (int e = 0; e < 8; e++) l[e] = acc[e] + bg[e];
        float mx = l[0];
#pragma unroll
        for (int e = 1; e < 8; e++) mx = fmaxf(mx, l[e]);
        float p[8], s = 0.f;
#pragma unroll
        for (int e = 0; e < 8; e++) { p[e] = expf(l[e] - mx); s += p[e]; }
        float inv = 1.f / s;
#pragma unroll
        for (int e = 0; e < 8; e++) p[e] *= inv;

        int i0 = 0; float v0 = p[0];
#pragma unroll
        for (int e = 1; e < 8; e++) if (p[e] > v0) { v0 = p[e]; i0 = e; }
        int i1 = -1; float v1 = -1.f;
#pragma unroll
        for (int e = 0; e < 8; e++) if (e != i0 && p[e] > v1) { v1 = p[e]; i1 = e; }

        float e1 = expf(v1 - v0);
        float den = 1.f / (1.f + e1);
        int p0 = atomicAdd(&g_count[i0], 1);
        g_slots[i0 * N_TOK + p0] = 2 * tok;
        int p1 = atomicAdd(&g_count[i1], 1);
        g_slots[i1 * N_TOK + p1] = 2 * tok + 1;
        g_topk_w[2 * tok]     = den;
        g_topk_w[2 * tok + 1] = e1 * den;
    }
}

// ---------------- ffn GEMM body: 128x128x64 tile, 3-stage ring,
// ---------------- cp.async spread in quarter-stages across the compute loop (de-bunch LSU)
template <bool FIRST>
__device__ __forceinline__ void ffn_body(int e, int m0, int n0,
                                         const float* __restrict__ Bias,
                                         float* __restrict__ out, char* smem) {
    constexpr int K  = FIRST ? D_IN : D_HID;
    constexpr int N  = FIRST ? D_HID : D_OUT;
    constexpr int BM = 128, BK = 64;
    constexpr int STRB = (BK + 8) * 2;     // 144 bytes/row
    constexpr int NS = K / BK;
    constexpr int ASTG = BM * STRB;        // 18432 B per stage

    constexpr int OFF_SLOT = 0;
    constexpr int OFF_A    = 1024;                 // 3 stages
    constexpr int OFF_B    = 1024 + 3 * ASTG;      // 3 stages

    const uint32_t su = s2u(smem);
    const int cnt = g_count[e];
    const int rows = min(BM, cnt - m0);

    const int tid  = threadIdx.x;
    const int lane = tid & 31;
    const int warp = tid >> 5;
    const int gid  = lane >> 2;
    const int itg  = lane & 3;
    const int wm = warp >> 1;
    const int wn = warp & 1;

    int* sSlot = (int*)(smem + OFF_SLOT);
    sSlot[tid] = g_slots[e * N_TOK + m0 + ((tid < rows) ? tid : 0)];
    __syncthreads();

    const __half* Wb = (FIRST ? g_W1h : g_W2h)
                     + (size_t)e * (size_t)N * K + (size_t)n0 * K;

    // quarter-stage: parts 0..3, each issues 4 cpa16/thread; commit at part 3.
    auto qstage = [&](int s, int part) {
        const int k0 = s * BK;
        const int sl = s % 3;
        const uint32_t ab = su + OFF_A + sl * ASTG;
        const uint32_t bb = su + OFF_B + sl * ASTG;
#pragma unroll
        for (int it = 2 * part; it < 2 * part + 2; it++) {   // A
            int idx = it * 128 + tid;
            int row = idx >> 3, c = idx & 7;
            int slot = sSlot[row];
            const __half* g = FIRST
                ? g_Xh + (size_t)(slot >> 1) * D_IN  + k0 + c * 8
                : g_Hh + (size_t)slot        * D_HID + k0 + c * 8;
            cpa16(ab + row * STRB + c * 16, g);
        }
#pragma unroll
        for (int it = 2 * part; it < 2 * part + 2; it++) {   // B
            int idx = it * 128 + tid;
            int row = idx >> 3, c = idx & 7;
            cpa16(bb + row * STRB + c * 16, Wb + (size_t)row * K + k0 + c * 8);
        }
        if (part == 3) asm volatile("cp.async.commit_group;\n");
    };
    auto stage = [&](int s) {
#pragma unroll
        for (int part = 0; part < 4; part++) qstage(s, part);
    };

    float acc[4][8][4];
#pragma unroll
    for (int a = 0; a < 4; a++)
#pragma unroll
        for (int b = 0; b < 8; b++)
#pragma unroll
            for (int c = 0; c < 4; c++) acc[a][b][c] = 0.f;

    const uint32_t aLane = (uint32_t)((wm * 64 + (lane & 15)) * STRB + (lane >> 4) * 16);
    const uint32_t bLane = (uint32_t)((wn * 64 + (lane & 7) + ((lane & 16) ? 8 : 0)) * STRB
                                      + ((lane & 8) ? 16 : 0));

    stage(0);
    stage(1);
    for (int s = 0; s < NS; ++s) {
        if (s + 1 < NS) {
            asm volatile("cp.async.wait_group 1;\n");
        } else {
            asm volatile("cp.async.wait_group 0;\n");
        }
        __syncthreads();

        const int sl = s % 3;
        const uint32_t aS = su + OFF_A + sl * ASTG + aLane;
        const uint32_t bS = su + OFF_B + sl * ASTG + bLane;

        uint32_t af[2][4][4], bf[2][4][4];
#pragma unroll
        for (int mf = 0; mf < 4; ++mf) LDSM_X4(af[0][mf], aS + mf * 16 * STRB);
#pragma unroll
        for (int p = 0; p < 4; ++p)    LDSM_X4(bf[0][p],  bS + p * 16 * STRB);

#pragma unroll
        for (int ks = 0; ks < BK / 16; ++ks) {
            const int cur = ks & 1, nxt = cur ^ 1;
            if (ks + 1 < BK / 16) {
#pragma unroll
                for (int mf = 0; mf < 4; ++mf)
                    LDSM_X4(af[nxt][mf], aS + (ks + 1) * 32 + mf * 16 * STRB);
#pragma unroll
                for (int p = 0; p < 4; ++p)
                    LDSM_X4(bf[nxt][p],  bS + (ks + 1) * 32 + p * 16 * STRB);
            }
            if (s + 2 < NS) qstage(s + 2, ks);   // spread next-next-stage loads
#pragma unroll
            for (int mf = 0; mf < 4; ++mf)
#pragma unroll
                for (int p = 0; p < 4; ++p) {
                    mma_f16(acc[mf][2 * p],     af[cur][mf], &bf[cur][p][0]);
                    mma_f16(acc[mf][2 * p + 1], af[cur][mf], &bf[cur][p][2]);
                }
        }
    }

#pragma unroll
    for (int mf = 0; mf < 4; ++mf) {
        int rl = wm * 64 + mf * 16 + gid;
#pragma unroll
        for (int nf = 0; nf < 8; ++nf) {
            int n = n0 + wn * 64 + nf * 8 + 2 * itg;
            float2 bv = *(const float2*)(Bias + (size_t)e * N + n);
            float v00 = acc[mf][nf][0] + bv.x;
            float v01 = acc[mf][nf][1] + bv.y;
            float v10 = acc[mf][nf][2] + bv.x;
            float v11 = acc[mf][nf][3] + bv.y;
            if (FIRST) {
                v00 = fmaxf(v00, 0.f); v01 = fmaxf(v01, 0.f);
                v10 = fmaxf(v10, 0.f); v11 = fmaxf(v11, 0.f);
                if (rl < rows) {
                    int slot = sSlot[rl];
                    *(half2*)(g_Hh + (size_t)slot * D_HID + n) = __floats2half2_rn(v00, v01);
                }
                if (rl + 8 < rows) {
                    int slot = sSlot[rl + 8];
                    *(half2*)(g_Hh + (size_t)slot * D_HID + n) = __floats2half2_rn(v10, v11);
                }
            } else {
                if (rl < rows) {
                    int slot = sSlot[rl];
                    float w = g_topk_w[slot];
                    float* o = out + (size_t)(slot >> 1) * D_OUT + n;
                    redadd(o,     v00 * w);
                    redadd(o + 1, v01 * w);
                }
                if (rl + 8 < rows) {
                    int slot = sSlot[rl + 8];
                    float w = g_topk_w[slot];
                    float* o = out + (size_t)(slot >> 1) * D_OUT + n;
                    redadd(o,     v10 * w);
                    redadd(o + 1, v11 * w);
                }
            }
        }
    }
}

// ---------------- F1: ffn layer 1 + batched ctW2 + out-zeroing ----------------
// bids [0,10240): 4 GEMM tiles : 1 ctW2 batch (bid%5). bids [10240,12288): zero out.
__global__ void __launch_bounds__(128, 2)
f1_kernel(const float* __restrict__ b1, const float* __restrict__ W2,
          float* __restrict__ out) {
    extern __shared__ __align__(128) char smem[];
    const int bid = blockIdx.x;
    if (bid >= 10240) {                     // ---- zero out (consumed only by f2's red.add) ----
        const int z = bid - 10240;
        float4* o = (float4*)out + (size_t)z * 512 + threadIdx.x;
#pragma unroll
        for (int q = 0; q < 4; q++) o[q * 128] = make_float4(0.f, 0.f, 0.f, 0.f);
        return;
    }
    const int i = bid / 5, r = bid % 5;
    if (r < 4) {
        const int j = i * 4 + r;            // f1 GEMM tile in [0,8192)
        const int nt = j & 31, mt = (j >> 5) & 31, e = j >> 10;
        if (mt * 128 >= g_count[e]) return;
        ffn_body<true>(e, mt * 128, nt * 128, b1, nullptr, smem);
    } else {
        float (*t)[65] = (float(*)[65])smem;
#pragma unroll
        for (int q = 0; q < 4; q++) {       // ctW2 batch: 4 consecutive tiles
            const int tl = i * 4 + q;
            const int e = tl >> 10, tile = tl & 1023;
            const int nt = tile & 15, kt = tile >> 4;
            if (q) __syncthreads();
            transpose_tile_128<D_HID, D_OUT>(W2 + (size_t)e * D_HID * D_OUT,
                                             g_W2h + (size_t)e * D_OUT * D_HID,
                                             nt * 64, kt * 64, t, threadIdx.x);
        }
    }
}

// ---------------- F2: ffn layer 2 (+fused combine via red.add) ----------------
__global__ void __launch_bounds__(128, 2)
f2_kernel(const float* __restrict__ b2, float* __restrict__ out) {
    extern __shared__ __align__(128) char smem[];
    const int e = blockIdx.z, mt = blockIdx.y, nt = blockIdx.x;
    if (mt * 128 >= g_count[e]) return;
    ffn_body<false>(e, mt * 128, nt * 128, b2, out, smem);
}

// ---------------- launch ----------------
extern "C" void kernel_launch(void* const* d_in, const int* in_sizes, int n_in,
                              void* d_out, int out_size) {
    const float* x  = (const float*)d_in[0];
    const float* W1 = (const float*)d_in[1];
    const float* b1 = (const float*)d_in[2];
    const float* W2 = (const float*)d_in[3];
    const float* b2 = (const float*)d_in[4];
    const float* Wg = (const float*)d_in[5];
    const float* bg = (const float*)d_in[6];
    float* out = (float*)d_out;

    constexpr int SMEM_FFN = 1024 + 6 * 128 * 144;   // 111616 -> 2 CTAs/SM
    cudaFuncSetAttribute(f1_kernel, cudaFuncAttributeMaxDynamicSharedMemorySize, SMEM_FFN);
    cudaFuncSetAttribute(f2_kernel, cudaFuncAttributeMaxDynamicSharedMemorySize, SMEM_FFN);

    init0_kernel<<<1, 32>>>();
    prep_kernel<<<2560, 256>>>(x, W1, Wg, bg);       // 2048 ctW1 batches + 512 gating
    f1_kernel<<<10240 + 2048, 128, SMEM_FFN>>>(b1, W2, out);
    f2_kernel<<<dim3(D_OUT / 128, N_TOK / 128, N_EXP), 128, SMEM_FFN>>>(b2, out);
}